// round 2
// baseline (speedup 1.0000x reference)
#include <cuda_runtime.h>

#define Bn 32768
#define Kn 8192
#define Dn 512
#define DECAYF 0.99f
#define OMDF   0.01f
#define EPSF   1e-5f

#define TM 128   // rows per block tile
#define TN 128   // codes per block tile
#define DKc 16   // D-chunk
#define SPAD 132 // padded smem row stride (floats), 16B aligned

// Scratch (allocation-free: __device__ globals)
__device__ float g_embed[(size_t)Kn * Dn];
__device__ float g_counts[Kn];
__device__ float g_csq[Kn];
__device__ int   g_idx[Bn];

// ---------------------------------------------------------------------------
// Zero the scatter accumulators (must run every launch; graph replays).
// ---------------------------------------------------------------------------
__global__ void zero_kernel() {
    int stride = gridDim.x * blockDim.x;
    int t = blockIdx.x * blockDim.x + threadIdx.x;
    const int N = Kn * Dn;
    for (int i = t; i < N; i += stride) g_embed[i] = 0.0f;
    if (t < Kn) g_counts[t] = 0.0f;
}

// ---------------------------------------------------------------------------
// Per-code squared norms: one warp per codebook row.
// ---------------------------------------------------------------------------
__global__ void csq_kernel(const float* __restrict__ cb) {
    int warp = (blockIdx.x * blockDim.x + threadIdx.x) >> 5;
    int lane = threadIdx.x & 31;
    if (warp >= Kn) return;
    const float4* row = (const float4*)(cb + (size_t)warp * Dn);
    float s = 0.0f;
    #pragma unroll
    for (int i = lane; i < Dn / 4; i += 32) {
        float4 v = row[i];
        s += v.x * v.x + v.y * v.y + v.z * v.z + v.w * v.w;
    }
    #pragma unroll
    for (int o = 16; o > 0; o >>= 1) s += __shfl_xor_sync(0xFFFFFFFFu, s, o);
    if (lane == 0) g_csq[warp] = s;
}

// ---------------------------------------------------------------------------
// Fused SGEMM + per-row argmin: score = c_sq[k] - 2 * <z_b, c_k>
// Block tile 128 rows x 128 codes, 8x8 per-thread register tile, fp32 FFMA.
// ---------------------------------------------------------------------------
__global__ void __launch_bounds__(256, 2)
argmin_kernel(const float* __restrict__ z_e, const float* __restrict__ cb) {
    __shared__ float As[DKc][SPAD];
    __shared__ float Bs[DKc][SPAD];
    __shared__ float csq_s[TN];
    __shared__ float redD[TM][16];
    __shared__ int   redI[TM][16];

    const int tid = threadIdx.x;
    const int tx = tid & 15;   // code group
    const int ty = tid >> 4;   // row group
    const int rowBase = blockIdx.x * TM;

    float bestD[8];
    int   bestI[8];
    #pragma unroll
    for (int i = 0; i < 8; i++) { bestD[i] = 3.4e38f; bestI[i] = 0; }

    for (int n = 0; n < Kn / TN; n++) {
        const int colBase = n * TN;

        __syncthreads();  // prior-iteration csq_s readers done
        if (tid < TN) csq_s[tid] = g_csq[colBase + tid];

        float acc[8][8];
        #pragma unroll
        for (int i = 0; i < 8; i++)
            #pragma unroll
            for (int j = 0; j < 8; j++) acc[i][j] = 0.0f;

        #pragma unroll 1
        for (int d0 = 0; d0 < Dn; d0 += DKc) {
            __syncthreads();  // prior compute done before overwriting tiles
            // Load A (128 x 16) and B (128 x 16), transposed into smem.
            #pragma unroll
            for (int it = 0; it < 2; it++) {
                int v = tid + it * 256;        // float4 index, 0..511
                int r = v >> 2;                // row within tile
                int c = (v & 3) * 4;           // d-offset within chunk
                float4 a = *(const float4*)(z_e + (size_t)(rowBase + r) * Dn + d0 + c);
                As[c + 0][r] = a.x; As[c + 1][r] = a.y;
                As[c + 2][r] = a.z; As[c + 3][r] = a.w;
                float4 b = *(const float4*)(cb + (size_t)(colBase + r) * Dn + d0 + c);
                Bs[c + 0][r] = b.x; Bs[c + 1][r] = b.y;
                Bs[c + 2][r] = b.z; Bs[c + 3][r] = b.w;
            }
            __syncthreads();

            #pragma unroll
            for (int kk = 0; kk < DKc; kk++) {
                float a[8], b[8];
                *(float4*)(a)     = *(const float4*)&As[kk][ty * 8];
                *(float4*)(a + 4) = *(const float4*)&As[kk][ty * 8 + 4];
                *(float4*)(b)     = *(const float4*)&Bs[kk][tx * 8];
                *(float4*)(b + 4) = *(const float4*)&Bs[kk][tx * 8 + 4];
                #pragma unroll
                for (int i = 0; i < 8; i++)
                    #pragma unroll
                    for (int j = 0; j < 8; j++)
                        acc[i][j] = fmaf(a[i], b[j], acc[i][j]);
            }
        }

        // Score and update running argmin (ascending code order within thread).
        #pragma unroll
        for (int j = 0; j < 8; j++) {
            float cs = csq_s[tx * 8 + j];
            int code = colBase + tx * 8 + j;
            #pragma unroll
            for (int i = 0; i < 8; i++) {
                float s = fmaf(-2.0f, acc[i][j], cs);
                if (s < bestD[i]) { bestD[i] = s; bestI[i] = code; }
            }
        }
    }

    __syncthreads();
    #pragma unroll
    for (int i = 0; i < 8; i++) {
        redD[ty * 8 + i][tx] = bestD[i];
        redI[ty * 8 + i][tx] = bestI[i];
    }
    __syncthreads();
    if (tid < TM) {
        float bd = redD[tid][0];
        int   bi = redI[tid][0];
        #pragma unroll
        for (int t = 1; t < 16; t++) {
            float d = redD[tid][t];
            int   ii = redI[tid][t];
            if (d < bd || (d == bd && ii < bi)) { bd = d; bi = ii; }
        }
        g_idx[rowBase + tid] = bi;
    }
}

// ---------------------------------------------------------------------------
// Gather z_q, write indices (as float), scatter counts / embed_sum.
// One block per z-row, 128 threads (4 floats each).
// ---------------------------------------------------------------------------
__global__ void scatter_kernel(const float* __restrict__ z_e,
                               const float* __restrict__ cb,
                               float* __restrict__ out) {
    const int b = blockIdx.x;
    const int t = threadIdx.x;
    const int idx = g_idx[b];

    const float4 z = ((const float4*)(z_e + (size_t)b * Dn))[t];
    const float4 c = ((const float4*)(cb + (size_t)idx * Dn))[t];
    ((float4*)(out + (size_t)b * Dn))[t] = c;   // z_q

    float* es = g_embed + (size_t)idx * Dn + t * 4;
    atomicAdd(es + 0, z.x);
    atomicAdd(es + 1, z.y);
    atomicAdd(es + 2, z.z);
    atomicAdd(es + 3, z.w);

    if (t == 0) {
        atomicAdd(&g_counts[idx], 1.0f);
        out[(size_t)Bn * Dn + b] = (float)idx;  // indices
    }
}

// ---------------------------------------------------------------------------
// EMA update: one block per code, 128 threads.
// ---------------------------------------------------------------------------
__global__ void ema_kernel(const float* __restrict__ ema_cs,
                           const float* __restrict__ ema_cb,
                           float* __restrict__ out) {
    const int k = blockIdx.x;
    const int t = threadIdx.x;

    const size_t offCb  = (size_t)Bn * Dn + Bn;       // new_codebook
    const size_t offCs  = offCb + (size_t)Kn * Dn;    // new_cluster_size
    const size_t offEma = offCs + Kn;                 // new_ema_codebook

    float ncs = DECAYF * ema_cs[k] + OMDF * g_counts[k];
    float inv = 1.0f / (ncs + EPSF);
    if (t == 0) out[offCs + k] = ncs;

    float4 ev = ((const float4*)(ema_cb + (size_t)k * Dn))[t];
    float4 sv = ((const float4*)(g_embed + (size_t)k * Dn))[t];
    float4 ne;
    ne.x = DECAYF * ev.x + OMDF * sv.x;
    ne.y = DECAYF * ev.y + OMDF * sv.y;
    ne.z = DECAYF * ev.z + OMDF * sv.z;
    ne.w = DECAYF * ev.w + OMDF * sv.w;
    ((float4*)(out + offEma + (size_t)k * Dn))[t] = ne;
    float4 nc;
    nc.x = ne.x * inv; nc.y = ne.y * inv; nc.z = ne.z * inv; nc.w = ne.w * inv;
    ((float4*)(out + offCb + (size_t)k * Dn))[t] = nc;
}

// ---------------------------------------------------------------------------
extern "C" void kernel_launch(void* const* d_in, const int* in_sizes, int n_in,
                              void* d_out, int out_size) {
    const float* z_e    = (const float*)d_in[0];
    const float* cb     = (const float*)d_in[1];
    const float* ema_cs = (const float*)d_in[2];
    const float* ema_cb = (const float*)d_in[3];
    float* out = (float*)d_out;

    zero_kernel<<<4096, 256>>>();
    csq_kernel<<<Kn / 8, 256>>>(cb);
    argmin_kernel<<<Bn / TM, 256>>>(z_e, cb);
    scatter_kernel<<<Bn, 128>>>(z_e, cb, out);
    ema_kernel<<<Kn, 128>>>(ema_cs, ema_cb, out);
}

// round 5
// speedup vs baseline: 1.3276x; 1.3276x over previous
#include <cuda_runtime.h>
#include <cuda_bf16.h>
#include <cstdint>

#define Bn 32768
#define Kn 8192
#define Dn 512
#define DECAYF 0.99f
#define OMDF   0.01f
#define EPSF   1e-5f

#define KCAT 1536            // 3 bf16 limbs x 512 per row
#define NITER 96             // 3072 / 32
#define AST 10240            // bytes per A stage: 128 rows * 80B
#define BST 10240
#define SM_CSQ  81920        // after 4*AST + 4*BST
#define SM_RED  82432
#define SMEM_BYTES 84480

// Device scratch (allocation-free). NEVER referenced from host code.
__device__ uint4 g_Acat4[(size_t)Bn * KCAT * 2 / 16];
__device__ uint4 g_Bcat4[(size_t)Kn * KCAT * 2 / 16];
__device__ float g_embed[(size_t)Kn * Dn];
__device__ float g_counts[Kn];
__device__ float g_csq[Kn];
__device__ unsigned long long g_best[Bn];

// limb pairings: (a0b0)(a0b1)(a1b0)(a1b1)(a0b2)(a2b0), offsets in elements
__constant__ int c_aoff[6] = {0, 0, 512, 512, 0, 1024};
__constant__ int c_boff[6] = {0, 512, 0, 512, 1024, 0};

__device__ __forceinline__ uint32_t smem_u32(const void* p) {
    uint32_t a;
    asm("{ .reg .u64 t; cvta.to.shared.u64 t, %1; cvt.u32.u64 %0, t; }"
        : "=r"(a) : "l"(p));
    return a;
}
__device__ __forceinline__ void cpa16(uint32_t s, const void* g) {
    asm volatile("cp.async.cg.shared.global [%0], [%1], 16;" :: "r"(s), "l"(g));
}
#define CP_COMMIT() asm volatile("cp.async.commit_group;" ::: "memory")
#define CP_WAIT2()  asm volatile("cp.async.wait_group 2;" ::: "memory")

__device__ __forceinline__ void ldsm4(uint32_t& r0, uint32_t& r1, uint32_t& r2,
                                      uint32_t& r3, uint32_t addr) {
    asm volatile("ldmatrix.sync.aligned.m8n8.x4.shared.b16 {%0,%1,%2,%3}, [%4];"
                 : "=r"(r0), "=r"(r1), "=r"(r2), "=r"(r3) : "r"(addr));
}
__device__ __forceinline__ void hmma(float* c, uint32_t a0, uint32_t a1,
                                     uint32_t a2, uint32_t a3,
                                     uint32_t b0, uint32_t b1) {
    asm volatile(
        "mma.sync.aligned.m16n8k16.row.col.f32.bf16.bf16.f32 "
        "{%0,%1,%2,%3}, {%4,%5,%6,%7}, {%8,%9}, {%0,%1,%2,%3};"
        : "+f"(c[0]), "+f"(c[1]), "+f"(c[2]), "+f"(c[3])
        : "r"(a0), "r"(a1), "r"(a2), "r"(a3), "r"(b0), "r"(b1));
}
__device__ __forceinline__ unsigned f2ord(float f) {
    unsigned u = __float_as_uint(f);
    return (u & 0x80000000u) ? ~u : (u | 0x80000000u);
}

// ---------------------------------------------------------------------------
__global__ void zero_kernel() {
    int stride = gridDim.x * blockDim.x;
    int t = blockIdx.x * blockDim.x + threadIdx.x;
    const int N = Kn * Dn;
    for (int i = t; i < N; i += stride) g_embed[i] = 0.0f;
    if (t < Kn) g_counts[t] = 0.0f;
    if (t < Bn) g_best[t] = 0xFFFFFFFFFFFFFFFFull;
}

// fp32 -> 3 exact bf16 limbs, [row][1536].
// Destination selected DEVICE-SIDE (host must not touch __device__ symbols).
__global__ void split_kernel(const float* __restrict__ src, int isA, int nElem) {
    __nv_bfloat16* dst = isA ? (__nv_bfloat16*)(void*)g_Acat4
                             : (__nv_bfloat16*)(void*)g_Bcat4;
    int stride = gridDim.x * blockDim.x;
    for (int i = blockIdx.x * blockDim.x + threadIdx.x; i < nElem; i += stride) {
        float x = src[i];
        __nv_bfloat16 b0 = __float2bfloat16(x);
        float r1 = x - __bfloat162float(b0);
        __nv_bfloat16 b1 = __float2bfloat16(r1);
        __nv_bfloat16 b2 = __float2bfloat16(r1 - __bfloat162float(b1));
        int row = i >> 9, c = i & 511;
        size_t base = (size_t)row * KCAT + c;
        dst[base]        = b0;
        dst[base + 512]  = b1;
        dst[base + 1024] = b2;
    }
}

__global__ void csq_kernel(const float* __restrict__ cb) {
    int warp = (blockIdx.x * blockDim.x + threadIdx.x) >> 5;
    int lane = threadIdx.x & 31;
    if (warp >= Kn) return;
    const float4* row = (const float4*)(cb + (size_t)warp * Dn);
    float s = 0.0f;
    #pragma unroll
    for (int i = lane; i < Dn / 4; i += 32) {
        float4 v = row[i];
        s += v.x * v.x + v.y * v.y + v.z * v.z + v.w * v.w;
    }
    #pragma unroll
    for (int o = 16; o > 0; o >>= 1) s += __shfl_xor_sync(0xFFFFFFFFu, s, o);
    if (lane == 0) g_csq[warp] = s;
}

// ---------------------------------------------------------------------------
// HMMA bf16x6 GEMM + per-row argmin, u64 atomicMin combine across col-tiles.
// Block 128x128, 8 warps (4x2), warp tile 32x64, BLK_K=32, 4-slot cp.async.
// ---------------------------------------------------------------------------
__global__ void __launch_bounds__(256, 2)
argmin_kernel() {
    extern __shared__ char sm[];
    const uint32_t sA = smem_u32(sm);
    const uint32_t sB = sA + 4 * AST;
    float* csq_s = (float*)(sm + SM_CSQ);
    unsigned long long* red = (unsigned long long*)(sm + SM_RED);

    const int tid = threadIdx.x;
    const int lane = tid & 31;
    const int w = tid >> 5;
    const int warpM = w & 3;       // 4 warps along M
    const int warpN = w >> 2;      // 2 warps along N
    const int rowTile = blockIdx.x >> 6;
    const int colTile = blockIdx.x & 63;   // colTile-fastest: codebook L2-resident
    const int rowBase = rowTile * 128;
    const int colBase = colTile * 128;

    if (tid < 128) csq_s[tid] = g_csq[colBase + tid];

    const __nv_bfloat16* A = (const __nv_bfloat16*)(void*)g_Acat4;
    const __nv_bfloat16* Bm = (const __nv_bfloat16*)(void*)g_Bcat4;

    // loader coords: each thread covers rows lr0 and lr0+64, 16B chunk lc
    const int lr0 = tid >> 2, lc = tid & 3;
    const int lr1 = lr0 + 64;
    const __nv_bfloat16* gA0 = A + (size_t)(rowBase + lr0) * KCAT + lc * 8;
    const __nv_bfloat16* gA1 = A + (size_t)(rowBase + lr1) * KCAT + lc * 8;
    const __nv_bfloat16* gB0 = Bm + (size_t)(colBase + lr0) * KCAT + lc * 8;
    const __nv_bfloat16* gB1 = Bm + (size_t)(colBase + lr1) * KCAT + lc * 8;
    const uint32_t soA0 = (uint32_t)(lr0 * 80 + lc * 16);
    const uint32_t soA1 = (uint32_t)(lr1 * 80 + lc * 16);

    float acc[2][8][4];
    #pragma unroll
    for (int mt = 0; mt < 2; mt++)
        #pragma unroll
        for (int nt = 0; nt < 8; nt++)
            #pragma unroll
            for (int r = 0; r < 4; r++) acc[mt][nt][r] = 0.0f;

    // ldmatrix lane addressing: mat0/1 = k-lo rows 0-15, mat2/3 = k-hi
    const int lrow = lane & 15;
    const int khalf = lane >> 4;
    const uint32_t aRowOff = (uint32_t)((warpM * 32 + lrow) * 80 + khalf * 16);
    const uint32_t bRowOff = (uint32_t)((warpN * 64 + lrow) * 80 + khalf * 16);

    #define LOAD_STAGE(s) do {                                                 \
        int _seg = (s) >> 4;                                                   \
        int _off = c_aoff[_seg] + (((s) & 15) << 5);                           \
        int _bof = c_boff[_seg] + (((s) & 15) << 5);                           \
        uint32_t _da = sA + ((s) & 3) * AST;                                   \
        uint32_t _db = sB + ((s) & 3) * BST;                                   \
        cpa16(_da + soA0, gA0 + _off);                                         \
        cpa16(_da + soA1, gA1 + _off);                                         \
        cpa16(_db + soA0, gB0 + _bof);                                         \
        cpa16(_db + soA1, gB1 + _bof);                                         \
    } while (0)

    LOAD_STAGE(0); CP_COMMIT();
    LOAD_STAGE(1); CP_COMMIT();
    LOAD_STAGE(2); CP_COMMIT();

    #pragma unroll 1
    for (int s = 0; s < NITER; s++) {
        CP_WAIT2();
        __syncthreads();
        if (s + 3 < NITER) LOAD_STAGE(s + 3);
        CP_COMMIT();

        const uint32_t da = sA + (s & 3) * AST;
        const uint32_t db = sB + (s & 3) * BST;
        #pragma unroll
        for (int k16 = 0; k16 < 2; k16++) {
            uint32_t a[2][4];
            #pragma unroll
            for (int mt = 0; mt < 2; mt++)
                ldsm4(a[mt][0], a[mt][1], a[mt][2], a[mt][3],
                      da + aRowOff + mt * 16 * 80 + k16 * 32);
            uint32_t b[4][4];
            #pragma unroll
            for (int np = 0; np < 4; np++)
                ldsm4(b[np][0], b[np][1], b[np][2], b[np][3],
                      db + bRowOff + np * 16 * 80 + k16 * 32);
            #pragma unroll
            for (int mt = 0; mt < 2; mt++)
                #pragma unroll
                for (int nt = 0; nt < 8; nt++)
                    hmma(acc[mt][nt],
                         a[mt][0], a[mt][1], a[mt][2], a[mt][3],
                         b[nt >> 1][(nt & 1) ? 1 : 0],   // k-lo: even n-oct r0, odd r1
                         b[nt >> 1][(nt & 1) ? 3 : 2]);  // k-hi: even r2, odd r3
        }
    }
    #undef LOAD_STAGE

    // epilogue: per-row argmin over this 128-code tile
    const int g = lane >> 2, tg = lane & 3;
    #pragma unroll
    for (int mt = 0; mt < 2; mt++) {
        #pragma unroll
        for (int half = 0; half < 2; half++) {
            int rloc = warpM * 32 + mt * 16 + half * 8 + g;
            unsigned long long best = 0xFFFFFFFFFFFFFFFFull;
            #pragma unroll
            for (int nt = 0; nt < 8; nt++) {
                #pragma unroll
                for (int cc = 0; cc < 2; cc++) {
                    float dot = acc[mt][nt][half * 2 + cc];
                    int col = warpN * 64 + nt * 8 + 2 * tg + cc;
                    float sc = fmaf(-2.0f, dot, csq_s[col]);
                    unsigned long long pk =
                        ((unsigned long long)f2ord(sc) << 32) |
                        (unsigned)(colBase + col);
                    if (pk < best) best = pk;
                }
            }
            unsigned long long o1 = __shfl_xor_sync(0xFFFFFFFFu, best, 1);
            if (o1 < best) best = o1;
            unsigned long long o2 = __shfl_xor_sync(0xFFFFFFFFu, best, 2);
            if (o2 < best) best = o2;
            if (tg == 0) red[rloc * 2 + warpN] = best;
        }
    }
    __syncthreads();
    if (tid < 128) {
        unsigned long long v = red[tid * 2];
        unsigned long long v2 = red[tid * 2 + 1];
        if (v2 < v) v = v2;
        atomicMin(&g_best[rowBase + tid], v);
    }
}

// ---------------------------------------------------------------------------
__global__ void scatter_kernel(const float* __restrict__ z_e,
                               const float* __restrict__ cb,
                               float* __restrict__ out) {
    const int b = blockIdx.x;
    const int t = threadIdx.x;
    const int idx = (int)(unsigned)(g_best[b] & 0xFFFFFFFFull);

    const float4 z = ((const float4*)(z_e + (size_t)b * Dn))[t];
    const float4 c = ((const float4*)(cb + (size_t)idx * Dn))[t];
    ((float4*)(out + (size_t)b * Dn))[t] = c;   // z_q

    float* es = g_embed + (size_t)idx * Dn + t * 4;
    atomicAdd(es + 0, z.x);
    atomicAdd(es + 1, z.y);
    atomicAdd(es + 2, z.z);
    atomicAdd(es + 3, z.w);

    if (t == 0) {
        atomicAdd(&g_counts[idx], 1.0f);
        out[(size_t)Bn * Dn + b] = (float)idx;  // indices
    }
}

__global__ void ema_kernel(const float* __restrict__ ema_cs,
                           const float* __restrict__ ema_cb,
                           float* __restrict__ out) {
    const int k = blockIdx.x;
    const int t = threadIdx.x;

    const size_t offCb  = (size_t)Bn * Dn + Bn;
    const size_t offCs  = offCb + (size_t)Kn * Dn;
    const size_t offEma = offCs + Kn;

    float ncs = DECAYF * ema_cs[k] + OMDF * g_counts[k];
    float inv = 1.0f / (ncs + EPSF);
    if (t == 0) out[offCs + k] = ncs;

    float4 ev = ((const float4*)(ema_cb + (size_t)k * Dn))[t];
    float4 sv = ((const float4*)(g_embed + (size_t)k * Dn))[t];
    float4 ne;
    ne.x = DECAYF * ev.x + OMDF * sv.x;
    ne.y = DECAYF * ev.y + OMDF * sv.y;
    ne.z = DECAYF * ev.z + OMDF * sv.z;
    ne.w = DECAYF * ev.w + OMDF * sv.w;
    ((float4*)(out + offEma + (size_t)k * Dn))[t] = ne;
    float4 nc;
    nc.x = ne.x * inv; nc.y = ne.y * inv; nc.z = ne.z * inv; nc.w = ne.w * inv;
    ((float4*)(out + offCb + (size_t)k * Dn))[t] = nc;
}

// ---------------------------------------------------------------------------
extern "C" void kernel_launch(void* const* d_in, const int* in_sizes, int n_in,
                              void* d_out, int out_size) {
    const float* z_e    = (const float*)d_in[0];
    const float* cb     = (const float*)d_in[1];
    const float* ema_cs = (const float*)d_in[2];
    const float* ema_cb = (const float*)d_in[3];
    float* out = (float*)d_out;

    cudaFuncSetAttribute(argmin_kernel,
                         cudaFuncAttributeMaxDynamicSharedMemorySize, SMEM_BYTES);

    zero_kernel<<<4096, 256>>>();
    split_kernel<<<8192, 256>>>(z_e, 1, Bn * Dn);   // -> g_Acat4 (device-side)
    split_kernel<<<2048, 256>>>(cb,  0, Kn * Dn);   // -> g_Bcat4 (device-side)
    csq_kernel<<<Kn / 8, 256>>>(cb);
    argmin_kernel<<<(Bn / 128) * (Kn / 128), 256, SMEM_BYTES>>>();
    scatter_kernel<<<Bn, 128>>>(z_e, cb, out);
    ema_kernel<<<Kn, 128>>>(ema_cs, ema_cb, out);
}

// round 6
// speedup vs baseline: 2.5611x; 1.9292x over previous
#include <cuda_runtime.h>
#include <cuda_fp16.h>
#include <cstdint>

#define Bn 32768
#define Kn 8192
#define Dn 512
#define DECAYF 0.99f
#define OMDF   0.01f
#define EPSF   1e-5f

#define KCAT 1024            // 2 fp16 limbs x 512 per row
#define NITER 48             // 1536 / 32  (3 limb-products x 512, BLK_K=32)
#define AST 10240            // bytes per A stage: 128 rows * 80B
#define BST 10240
#define SM_CSQ  81920        // after 4*AST + 4*BST
#define SM_RED  82432
#define SMEM_BYTES 84480

// Device scratch (allocation-free). NEVER referenced from host code.
__device__ uint4 g_Acat4[(size_t)Bn * KCAT * 2 / 16];
__device__ uint4 g_Bcat4[(size_t)Kn * KCAT * 2 / 16];
__device__ float g_embed[(size_t)Kn * Dn];
__device__ float g_counts[Kn];
__device__ float g_csq[Kn];
__device__ unsigned long long g_best[Bn];

// limb pairings for fp16x3: (a0b0)(a0b1)(a1b0); a1b1 dropped (~2^-22 rel)
__constant__ int c_aoff[3] = {0, 0, 512};
__constant__ int c_boff[3] = {0, 512, 0};

__device__ __forceinline__ uint32_t smem_u32(const void* p) {
    uint32_t a;
    asm("{ .reg .u64 t; cvta.to.shared.u64 t, %1; cvt.u32.u64 %0, t; }"
        : "=r"(a) : "l"(p));
    return a;
}
__device__ __forceinline__ void cpa16(uint32_t s, const void* g) {
    asm volatile("cp.async.cg.shared.global [%0], [%1], 16;" :: "r"(s), "l"(g));
}
#define CP_COMMIT() asm volatile("cp.async.commit_group;" ::: "memory")
#define CP_WAIT2()  asm volatile("cp.async.wait_group 2;" ::: "memory")

__device__ __forceinline__ void ldsm4(uint32_t& r0, uint32_t& r1, uint32_t& r2,
                                      uint32_t& r3, uint32_t addr) {
    asm volatile("ldmatrix.sync.aligned.m8n8.x4.shared.b16 {%0,%1,%2,%3}, [%4];"
                 : "=r"(r0), "=r"(r1), "=r"(r2), "=r"(r3) : "r"(addr));
}
__device__ __forceinline__ void hmma(float* c, uint32_t a0, uint32_t a1,
                                     uint32_t a2, uint32_t a3,
                                     uint32_t b0, uint32_t b1) {
    asm volatile(
        "mma.sync.aligned.m16n8k16.row.col.f32.f16.f16.f32 "
        "{%0,%1,%2,%3}, {%4,%5,%6,%7}, {%8,%9}, {%0,%1,%2,%3};"
        : "+f"(c[0]), "+f"(c[1]), "+f"(c[2]), "+f"(c[3])
        : "r"(a0), "r"(a1), "r"(a2), "r"(a3), "r"(b0), "r"(b1));
}
__device__ __forceinline__ unsigned f2ord(float f) {
    unsigned u = __float_as_uint(f);
    return (u & 0x80000000u) ? ~u : (u | 0x80000000u);
}

// ---------------------------------------------------------------------------
__global__ void zero_kernel() {
    int stride = gridDim.x * blockDim.x;
    int t = blockIdx.x * blockDim.x + threadIdx.x;
    const int N = Kn * Dn;
    for (int i = t; i < N; i += stride) g_embed[i] = 0.0f;
    if (t < Kn) g_counts[t] = 0.0f;
    if (t < Bn) g_best[t] = 0xFFFFFFFFFFFFFFFFull;
}

// fp32 -> 2 exact fp16 limbs, [row][1024].
// Destination selected DEVICE-SIDE (host must not touch __device__ symbols).
__global__ void split_kernel(const float* __restrict__ src, int isA, int nElem) {
    __half* dst = isA ? (__half*)(void*)g_Acat4 : (__half*)(void*)g_Bcat4;
    int stride = gridDim.x * blockDim.x;
    for (int i = blockIdx.x * blockDim.x + threadIdx.x; i < nElem; i += stride) {
        float x = src[i];
        __half h0 = __float2half_rn(x);
        __half h1 = __float2half_rn(x - __half2float(h0));
        int row = i >> 9, c = i & 511;
        size_t base = (size_t)row * KCAT + c;
        dst[base]       = h0;
        dst[base + 512] = h1;
    }
}

__global__ void csq_kernel(const float* __restrict__ cb) {
    int warp = (blockIdx.x * blockDim.x + threadIdx.x) >> 5;
    int lane = threadIdx.x & 31;
    if (warp >= Kn) return;
    const float4* row = (const float4*)(cb + (size_t)warp * Dn);
    float s = 0.0f;
    #pragma unroll
    for (int i = lane; i < Dn / 4; i += 32) {
        float4 v = row[i];
        s += v.x * v.x + v.y * v.y + v.z * v.z + v.w * v.w;
    }
    #pragma unroll
    for (int o = 16; o > 0; o >>= 1) s += __shfl_xor_sync(0xFFFFFFFFu, s, o);
    if (lane == 0) g_csq[warp] = s;
}

// ---------------------------------------------------------------------------
// HMMA fp16x3 GEMM + per-row argmin, u64 atomicMin combine across col-tiles.
// Block 128x128, 8 warps (4x2), warp tile 32x64, BLK_K=32, 4-slot cp.async.
// ---------------------------------------------------------------------------
__global__ void __launch_bounds__(256, 2)
argmin_kernel() {
    extern __shared__ char sm[];
    const uint32_t sA = smem_u32(sm);
    const uint32_t sB = sA + 4 * AST;
    float* csq_s = (float*)(sm + SM_CSQ);
    unsigned long long* red = (unsigned long long*)(sm + SM_RED);

    const int tid = threadIdx.x;
    const int lane = tid & 31;
    const int w = tid >> 5;
    const int warpM = w & 3;
    const int warpN = w >> 2;
    const int rowTile = blockIdx.x >> 6;
    const int colTile = blockIdx.x & 63;   // colTile-fastest: codebook L2-resident
    const int rowBase = rowTile * 128;
    const int colBase = colTile * 128;

    if (tid < 128) csq_s[tid] = g_csq[colBase + tid];

    const __half* A = (const __half*)(void*)g_Acat4;
    const __half* Bm = (const __half*)(void*)g_Bcat4;

    const int lr0 = tid >> 2, lc = tid & 3;
    const int lr1 = lr0 + 64;
    const __half* gA0 = A + (size_t)(rowBase + lr0) * KCAT + lc * 8;
    const __half* gA1 = A + (size_t)(rowBase + lr1) * KCAT + lc * 8;
    const __half* gB0 = Bm + (size_t)(colBase + lr0) * KCAT + lc * 8;
    const __half* gB1 = Bm + (size_t)(colBase + lr1) * KCAT + lc * 8;
    const uint32_t soA0 = (uint32_t)(lr0 * 80 + lc * 16);
    const uint32_t soA1 = (uint32_t)(lr1 * 80 + lc * 16);

    float acc[2][8][4];
    #pragma unroll
    for (int mt = 0; mt < 2; mt++)
        #pragma unroll
        for (int nt = 0; nt < 8; nt++)
            #pragma unroll
            for (int r = 0; r < 4; r++) acc[mt][nt][r] = 0.0f;

    const int lrow = lane & 15;
    const int khalf = lane >> 4;
    const uint32_t aRowOff = (uint32_t)((warpM * 32 + lrow) * 80 + khalf * 16);
    const uint32_t bRowOff = (uint32_t)((warpN * 64 + lrow) * 80 + khalf * 16);

    #define LOAD_STAGE(s) do {                                                 \
        int _seg = (s) >> 4;                                                   \
        int _off = c_aoff[_seg] + (((s) & 15) << 5);                           \
        int _bof = c_boff[_seg] + (((s) & 15) << 5);                           \
        uint32_t _da = sA + ((s) & 3) * AST;                                   \
        uint32_t _db = sB + ((s) & 3) * BST;                                   \
        cpa16(_da + soA0, gA0 + _off);                                         \
        cpa16(_da + soA1, gA1 + _off);                                         \
        cpa16(_db + soA0, gB0 + _bof);                                         \
        cpa16(_db + soA1, gB1 + _bof);                                         \
    } while (0)

    LOAD_STAGE(0); CP_COMMIT();
    LOAD_STAGE(1); CP_COMMIT();
    LOAD_STAGE(2); CP_COMMIT();

    #pragma unroll 1
    for (int s = 0; s < NITER; s++) {
        CP_WAIT2();
        __syncthreads();
        if (s + 3 < NITER) LOAD_STAGE(s + 3);
        CP_COMMIT();

        const uint32_t da = sA + (s & 3) * AST;
        const uint32_t db = sB + (s & 3) * BST;
        #pragma unroll
        for (int k16 = 0; k16 < 2; k16++) {
            uint32_t a[2][4];
            #pragma unroll
            for (int mt = 0; mt < 2; mt++)
                ldsm4(a[mt][0], a[mt][1], a[mt][2], a[mt][3],
                      da + aRowOff + mt * 16 * 80 + k16 * 32);
            uint32_t b[4][4];
            #pragma unroll
            for (int np = 0; np < 4; np++)
                ldsm4(b[np][0], b[np][1], b[np][2], b[np][3],
                      db + bRowOff + np * 16 * 80 + k16 * 32);
            #pragma unroll
            for (int mt = 0; mt < 2; mt++)
                #pragma unroll
                for (int nt = 0; nt < 8; nt++)
                    hmma(acc[mt][nt],
                         a[mt][0], a[mt][1], a[mt][2], a[mt][3],
                         b[nt >> 1][(nt & 1) ? 1 : 0],
                         b[nt >> 1][(nt & 1) ? 3 : 2]);
        }
    }
    #undef LOAD_STAGE

    // epilogue: per-row argmin over this 128-code tile
    const int g = lane >> 2, tg = lane & 3;
    #pragma unroll
    for (int mt = 0; mt < 2; mt++) {
        #pragma unroll
        for (int half = 0; half < 2; half++) {
            int rloc = warpM * 32 + mt * 16 + half * 8 + g;
            unsigned long long best = 0xFFFFFFFFFFFFFFFFull;
            #pragma unroll
            for (int nt = 0; nt < 8; nt++) {
                #pragma unroll
                for (int cc = 0; cc < 2; cc++) {
                    float dot = acc[mt][nt][half * 2 + cc];
                    int col = warpN * 64 + nt * 8 + 2 * tg + cc;
                    float sc = fmaf(-2.0f, dot, csq_s[col]);
                    unsigned long long pk =
                        ((unsigned long long)f2ord(sc) << 32) |
                        (unsigned)(colBase + col);
                    if (pk < best) best = pk;
                }
            }
            unsigned long long o1 = __shfl_xor_sync(0xFFFFFFFFu, best, 1);
            if (o1 < best) best = o1;
            unsigned long long o2 = __shfl_xor_sync(0xFFFFFFFFu, best, 2);
            if (o2 < best) best = o2;
            if (tg == 0) red[rloc * 2 + warpN] = best;
        }
    }
    __syncthreads();
    if (tid < 128) {
        unsigned long long v = red[tid * 2];
        unsigned long long v2 = red[tid * 2 + 1];
        if (v2 < v) v = v2;
        atomicMin(&g_best[rowBase + tid], v);
    }
}

// ---------------------------------------------------------------------------
__global__ void scatter_kernel(const float* __restrict__ z_e,
                               const float* __restrict__ cb,
                               float* __restrict__ out) {
    const int b = blockIdx.x;
    const int t = threadIdx.x;
    const int idx = (int)(unsigned)(g_best[b] & 0xFFFFFFFFull);

    const float4 z = ((const float4*)(z_e + (size_t)b * Dn))[t];
    const float4 c = ((const float4*)(cb + (size_t)idx * Dn))[t];
    ((float4*)(out + (size_t)b * Dn))[t] = c;   // z_q

    float* es = g_embed + (size_t)idx * Dn + t * 4;
    atomicAdd(es + 0, z.x);
    atomicAdd(es + 1, z.y);
    atomicAdd(es + 2, z.z);
    atomicAdd(es + 3, z.w);

    if (t == 0) {
        atomicAdd(&g_counts[idx], 1.0f);
        out[(size_t)Bn * Dn + b] = (float)idx;  // indices
    }
}

__global__ void ema_kernel(const float* __restrict__ ema_cs,
                           const float* __restrict__ ema_cb,
                           float* __restrict__ out) {
    const int k = blockIdx.x;
    const int t = threadIdx.x;

    const size_t offCb  = (size_t)Bn * Dn + Bn;
    const size_t offCs  = offCb + (size_t)Kn * Dn;
    const size_t offEma = offCs + Kn;

    float ncs = DECAYF * ema_cs[k] + OMDF * g_counts[k];
    float inv = 1.0f / (ncs + EPSF);
    if (t == 0) out[offCs + k] = ncs;

    float4 ev = ((const float4*)(ema_cb + (size_t)k * Dn))[t];
    float4 sv = ((const float4*)(g_embed + (size_t)k * Dn))[t];
    float4 ne;
    ne.x = DECAYF * ev.x + OMDF * sv.x;
    ne.y = DECAYF * ev.y + OMDF * sv.y;
    ne.z = DECAYF * ev.z + OMDF * sv.z;
    ne.w = DECAYF * ev.w + OMDF * sv.w;
    ((float4*)(out + offEma + (size_t)k * Dn))[t] = ne;
    float4 nc;
    nc.x = ne.x * inv; nc.y = ne.y * inv; nc.z = ne.z * inv; nc.w = ne.w * inv;
    ((float4*)(out + offCb + (size_t)k * Dn))[t] = nc;
}

// ---------------------------------------------------------------------------
extern "C" void kernel_launch(void* const* d_in, const int* in_sizes, int n_in,
                              void* d_out, int out_size) {
    const float* z_e    = (const float*)d_in[0];
    const float* cb     = (const float*)d_in[1];
    const float* ema_cs = (const float*)d_in[2];
    const float* ema_cb = (const float*)d_in[3];
    float* out = (float*)d_out;

    cudaFuncSetAttribute(argmin_kernel,
                         cudaFuncAttributeMaxDynamicSharedMemorySize, SMEM_BYTES);

    zero_kernel<<<4096, 256>>>();
    split_kernel<<<8192, 256>>>(z_e, 1, Bn * Dn);   // -> g_Acat4 (device-side)
    split_kernel<<<2048, 256>>>(cb,  0, Kn * Dn);   // -> g_Bcat4 (device-side)
    csq_kernel<<<Kn / 8, 256>>>(cb);
    argmin_kernel<<<(Bn / 128) * (Kn / 128), 256, SMEM_BYTES>>>();
    scatter_kernel<<<Bn, 128>>>(z_e, cb, out);
    ema_kernel<<<Kn, 128>>>(ema_cs, ema_cb, out);
}

// round 7
// speedup vs baseline: 5.3267x; 2.0798x over previous
#include <cuda_runtime.h>
#include <cuda_fp16.h>
#include <cstdint>

#define Bn 32768
#define Kn 8192
#define Dn 512
#define DECAYF 0.99f
#define OMDF   0.01f
#define EPSF   1e-5f

#define NITER 16             // K=512, BLK_K=32
#define AST 10240            // 128 rows * 80B
#define BST 10240
#define SM_CSQ  81920
#define SMEM_BYTES 82944

// Device scratch (allocation-free). NEVER referenced from host code.
__device__ uint4  g_A4[(size_t)Bn * Dn * 2 / 16];     // fp16 h0 of z_e
__device__ uint4  g_B4[(size_t)Kn * Dn * 2 / 16];     // fp16 h0 of codebook
__device__ __half g_scores[(size_t)Bn * Kn];          // 512MB approx scores
__device__ float  g_embed[(size_t)Kn * Dn];
__device__ float  g_counts[Kn];
__device__ float  g_csq[Kn];
__device__ unsigned g_cmax_bits;                      // max csq (float bits)
__device__ int    g_idx[Bn];

__device__ __forceinline__ uint32_t smem_u32(const void* p) {
    uint32_t a;
    asm("{ .reg .u64 t; cvta.to.shared.u64 t, %1; cvt.u32.u64 %0, t; }"
        : "=r"(a) : "l"(p));
    return a;
}
__device__ __forceinline__ void cpa16(uint32_t s, const void* g) {
    asm volatile("cp.async.cg.shared.global [%0], [%1], 16;" :: "r"(s), "l"(g));
}
#define CP_COMMIT() asm volatile("cp.async.commit_group;" ::: "memory")
#define CP_WAIT2()  asm volatile("cp.async.wait_group 2;" ::: "memory")

__device__ __forceinline__ void ldsm4(uint32_t& r0, uint32_t& r1, uint32_t& r2,
                                      uint32_t& r3, uint32_t addr) {
    asm volatile("ldmatrix.sync.aligned.m8n8.x4.shared.b16 {%0,%1,%2,%3}, [%4];"
                 : "=r"(r0), "=r"(r1), "=r"(r2), "=r"(r3) : "r"(addr));
}
__device__ __forceinline__ void hmma(float* c, uint32_t a0, uint32_t a1,
                                     uint32_t a2, uint32_t a3,
                                     uint32_t b0, uint32_t b1) {
    asm volatile(
        "mma.sync.aligned.m16n8k16.row.col.f32.f16.f16.f32 "
        "{%0,%1,%2,%3}, {%4,%5,%6,%7}, {%8,%9}, {%0,%1,%2,%3};"
        : "+f"(c[0]), "+f"(c[1]), "+f"(c[2]), "+f"(c[3])
        : "r"(a0), "r"(a1), "r"(a2), "r"(a3), "r"(b0), "r"(b1));
}
__device__ __forceinline__ unsigned f2ord(float f) {
    unsigned u = __float_as_uint(f);
    return (u & 0x80000000u) ? ~u : (u | 0x80000000u);
}

// ---------------------------------------------------------------------------
__global__ void zero_kernel() {
    int stride = gridDim.x * blockDim.x;
    int t = blockIdx.x * blockDim.x + threadIdx.x;
    const int N = Kn * Dn;
    for (int i = t; i < N; i += stride) g_embed[i] = 0.0f;
    if (t < Kn) g_counts[t] = 0.0f;
    if (t == 0) g_cmax_bits = 0u;
}

// fp32 -> fp16 (h0 only), linear layout [row][512]
__global__ void split_kernel(const float* __restrict__ src, int isA, int nElem) {
    __half* dst = isA ? (__half*)(void*)g_A4 : (__half*)(void*)g_B4;
    int stride = gridDim.x * blockDim.x;
    for (int i = blockIdx.x * blockDim.x + threadIdx.x; i < nElem; i += stride)
        dst[i] = __float2half_rn(src[i]);
}

__global__ void csq_kernel(const float* __restrict__ cb) {
    int warp = (blockIdx.x * blockDim.x + threadIdx.x) >> 5;
    int lane = threadIdx.x & 31;
    if (warp >= Kn) return;
    const float4* row = (const float4*)(cb + (size_t)warp * Dn);
    float s = 0.0f;
    #pragma unroll
    for (int i = lane; i < Dn / 4; i += 32) {
        float4 v = row[i];
        s += v.x * v.x + v.y * v.y + v.z * v.z + v.w * v.w;
    }
    #pragma unroll
    for (int o = 16; o > 0; o >>= 1) s += __shfl_xor_sync(0xFFFFFFFFu, s, o);
    if (lane == 0) {
        g_csq[warp] = s;
        atomicMax(&g_cmax_bits, __float_as_uint(s));  // s > 0: bit order = float order
    }
}

// ---------------------------------------------------------------------------
// Pass 1: fp16 h0-only GEMM, scores (csq - 2*dot) written to g_scores as fp16.
// Block 128x128, 8 warps (4x2), warp tile 32x64, BLK_K=32, 4-slot cp.async.
// ---------------------------------------------------------------------------
__global__ void __launch_bounds__(256, 2)
gemm_kernel() {
    extern __shared__ char sm[];
    const uint32_t sA = smem_u32(sm);
    const uint32_t sB = sA + 4 * AST;
    float* csq_s = (float*)(sm + SM_CSQ);

    const int tid = threadIdx.x;
    const int lane = tid & 31;
    const int w = tid >> 5;
    const int warpM = w & 3;
    const int warpN = w >> 2;
    const int rowTile = blockIdx.x >> 6;
    const int colTile = blockIdx.x & 63;
    const int rowBase = rowTile * 128;
    const int colBase = colTile * 128;

    if (tid < 128) csq_s[tid] = g_csq[colBase + tid];

    const __half* A = (const __half*)(void*)g_A4;
    const __half* Bm = (const __half*)(void*)g_B4;

    const int lr0 = tid >> 2, lc = tid & 3;
    const int lr1 = lr0 + 64;
    const __half* gA0 = A + (size_t)(rowBase + lr0) * Dn + lc * 8;
    const __half* gA1 = A + (size_t)(rowBase + lr1) * Dn + lc * 8;
    const __half* gB0 = Bm + (size_t)(colBase + lr0) * Dn + lc * 8;
    const __half* gB1 = Bm + (size_t)(colBase + lr1) * Dn + lc * 8;
    const uint32_t soA0 = (uint32_t)(lr0 * 80 + lc * 16);
    const uint32_t soA1 = (uint32_t)(lr1 * 80 + lc * 16);

    float acc[2][8][4];
    #pragma unroll
    for (int mt = 0; mt < 2; mt++)
        #pragma unroll
        for (int nt = 0; nt < 8; nt++)
            #pragma unroll
            for (int r = 0; r < 4; r++) acc[mt][nt][r] = 0.0f;

    const int lrow = lane & 15;
    const int khalf = lane >> 4;
    const uint32_t aRowOff = (uint32_t)((warpM * 32 + lrow) * 80 + khalf * 16);
    const uint32_t bRowOff = (uint32_t)((warpN * 64 + lrow) * 80 + khalf * 16);

    #define LOAD_STAGE(s) do {                                                 \
        int _off = (s) << 5;                                                   \
        uint32_t _da = sA + ((s) & 3) * AST;                                   \
        uint32_t _db = sB + ((s) & 3) * BST;                                   \
        cpa16(_da + soA0, gA0 + _off);                                         \
        cpa16(_da + soA1, gA1 + _off);                                         \
        cpa16(_db + soA0, gB0 + _off);                                         \
        cpa16(_db + soA1, gB1 + _off);                                         \
    } while (0)

    LOAD_STAGE(0); CP_COMMIT();
    LOAD_STAGE(1); CP_COMMIT();
    LOAD_STAGE(2); CP_COMMIT();

    #pragma unroll 1
    for (int s = 0; s < NITER; s++) {
        CP_WAIT2();
        __syncthreads();
        if (s + 3 < NITER) LOAD_STAGE(s + 3);
        CP_COMMIT();

        const uint32_t da = sA + (s & 3) * AST;
        const uint32_t db = sB + (s & 3) * BST;
        #pragma unroll
        for (int k16 = 0; k16 < 2; k16++) {
            uint32_t a[2][4];
            #pragma unroll
            for (int mt = 0; mt < 2; mt++)
                ldsm4(a[mt][0], a[mt][1], a[mt][2], a[mt][3],
                      da + aRowOff + mt * 16 * 80 + k16 * 32);
            uint32_t b[4][4];
            #pragma unroll
            for (int np = 0; np < 4; np++)
                ldsm4(b[np][0], b[np][1], b[np][2], b[np][3],
                      db + bRowOff + np * 16 * 80 + k16 * 32);
            #pragma unroll
            for (int mt = 0; mt < 2; mt++)
                #pragma unroll
                for (int nt = 0; nt < 8; nt++)
                    hmma(acc[mt][nt],
                         a[mt][0], a[mt][1], a[mt][2], a[mt][3],
                         b[nt >> 1][(nt & 1) ? 1 : 0],
                         b[nt >> 1][(nt & 1) ? 3 : 2]);
        }
    }
    #undef LOAD_STAGE

    // epilogue: score = csq - 2*dot, write fp16 pairs
    const int g = lane >> 2, tg = lane & 3;
    #pragma unroll
    for (int mt = 0; mt < 2; mt++) {
        #pragma unroll
        for (int half = 0; half < 2; half++) {
            int grow = rowBase + warpM * 32 + mt * 16 + half * 8 + g;
            __half2* dst = (__half2*)(g_scores + (size_t)grow * Kn + colBase);
            #pragma unroll
            for (int nt = 0; nt < 8; nt++) {
                int cl = warpN * 64 + nt * 8 + tg * 2;
                float s0 = fmaf(-2.0f, acc[mt][nt][half * 2 + 0], csq_s[cl]);
                float s1 = fmaf(-2.0f, acc[mt][nt][half * 2 + 1], csq_s[cl + 1]);
                dst[cl >> 1] = __floats2half2_rn(s0, s1);
            }
        }
    }
}

// ---------------------------------------------------------------------------
// Pass 2: per-row scan of approx scores, candidate gather, exact fp32 rescore.
// One block of 256 threads per row.
// ---------------------------------------------------------------------------
#define MAXCAND 128
__global__ void __launch_bounds__(256)
select_kernel(const float* __restrict__ z_e, const float* __restrict__ cb) {
    __shared__ float zs[Dn];
    __shared__ float rz[8], rs[8];
    __shared__ int list[MAXCAND];
    __shared__ int cnt;
    __shared__ float thrS;
    __shared__ unsigned long long bestPk;

    const int row = blockIdx.x;
    const int t = threadIdx.x;
    const int lane = t & 31, wid = t >> 5;

    // load z row + zsq
    float2 zv = ((const float2*)(z_e + (size_t)row * Dn))[t];
    ((float2*)zs)[t] = zv;
    float zp = zv.x * zv.x + zv.y * zv.y;
    #pragma unroll
    for (int o = 16; o > 0; o >>= 1) zp += __shfl_xor_sync(0xFFFFFFFFu, zp, o);
    if (lane == 0) rz[wid] = zp;
    if (t == 0) { cnt = 0; bestPk = 0xFFFFFFFFFFFFFFFFull; }

    // load 32 scores (strided, coalesced), track min
    const __half* sr = g_scores + (size_t)row * Kn;
    float sc[32];
    float mn = 3.4e38f;
    #pragma unroll
    for (int i = 0; i < 32; i++) {
        sc[i] = __half2float(sr[t + (i << 8)]);
        mn = fminf(mn, sc[i]);
    }
    #pragma unroll
    for (int o = 16; o > 0; o >>= 1) mn = fminf(mn, __shfl_xor_sync(0xFFFFFFFFu, mn, o));
    if (lane == 0) rs[wid] = mn;
    __syncthreads();
    if (t == 0) {
        float zsq = 0.0f, m = 3.4e38f;
        #pragma unroll
        for (int i = 0; i < 8; i++) { zsq += rz[i]; m = fminf(m, rs[i]); }
        float cmax = __uint_as_float(g_cmax_bits);
        // sound margin: dropped-products bound + fp16 quantization + slack
        thrS = m + 0.001953125f * sqrtf(zsq * cmax) + 4.5f;
    }
    __syncthreads();

    const float thr = thrS;
    #pragma unroll
    for (int i = 0; i < 32; i++) {
        if (sc[i] <= thr) {
            int p = atomicAdd(&cnt, 1);
            if (p < MAXCAND) list[p] = t + (i << 8);
        }
    }
    __syncthreads();

    if (cnt <= MAXCAND) {
        // warp-cooperative exact rescore of each candidate
        const int n = cnt;
        for (int j = wid; j < n; j += 8) {
            const int k = list[j];
            const float4* crow = (const float4*)(cb + (size_t)k * Dn);
            const float4* zrow = (const float4*)zs;
            float d = 0.0f;
            #pragma unroll
            for (int c = lane; c < Dn / 4; c += 32) {
                float4 a = zrow[c], b = crow[c];
                d += a.x * b.x + a.y * b.y + a.z * b.z + a.w * b.w;
            }
            #pragma unroll
            for (int o = 16; o > 0; o >>= 1) d += __shfl_xor_sync(0xFFFFFFFFu, d, o);
            if (lane == 0) {
                float ex = fmaf(-2.0f, d, g_csq[k]);
                unsigned long long pk =
                    ((unsigned long long)f2ord(ex) << 32) | (unsigned)k;
                atomicMin(&bestPk, pk);
            }
        }
    } else {
        // pathological overflow: exact brute force over all K (sound fallback)
        for (int k = t; k < Kn; k += 256) {
            const float* crow = cb + (size_t)k * Dn;
            float d = 0.0f;
            for (int c = 0; c < Dn; c++) d += zs[c] * crow[c];
            float ex = fmaf(-2.0f, d, g_csq[k]);
            unsigned long long pk =
                ((unsigned long long)f2ord(ex) << 32) | (unsigned)k;
            atomicMin(&bestPk, pk);
        }
    }
    __syncthreads();
    if (t == 0) g_idx[row] = (int)(unsigned)(bestPk & 0xFFFFFFFFull);
}

// ---------------------------------------------------------------------------
__global__ void scatter_kernel(const float* __restrict__ z_e,
                               const float* __restrict__ cb,
                               float* __restrict__ out) {
    const int b = blockIdx.x;
    const int t = threadIdx.x;
    const int idx = g_idx[b];

    const float4 z = ((const float4*)(z_e + (size_t)b * Dn))[t];
    const float4 c = ((const float4*)(cb + (size_t)idx * Dn))[t];
    ((float4*)(out + (size_t)b * Dn))[t] = c;   // z_q

    float* es = g_embed + (size_t)idx * Dn + t * 4;
    atomicAdd(es + 0, z.x);
    atomicAdd(es + 1, z.y);
    atomicAdd(es + 2, z.z);
    atomicAdd(es + 3, z.w);

    if (t == 0) {
        atomicAdd(&g_counts[idx], 1.0f);
        out[(size_t)Bn * Dn + b] = (float)idx;  // indices
    }
}

__global__ void ema_kernel(const float* __restrict__ ema_cs,
                           const float* __restrict__ ema_cb,
                           float* __restrict__ out) {
    const int k = blockIdx.x;
    const int t = threadIdx.x;

    const size_t offCb  = (size_t)Bn * Dn + Bn;
    const size_t offCs  = offCb + (size_t)Kn * Dn;
    const size_t offEma = offCs + Kn;

    float ncs = DECAYF * ema_cs[k] + OMDF * g_counts[k];
    float inv = 1.0f / (ncs + EPSF);
    if (t == 0) out[offCs + k] = ncs;

    float4 ev = ((const float4*)(ema_cb + (size_t)k * Dn))[t];
    float4 sv = ((const float4*)(g_embed + (size_t)k * Dn))[t];
    float4 ne;
    ne.x = DECAYF * ev.x + OMDF * sv.x;
    ne.y = DECAYF * ev.y + OMDF * sv.y;
    ne.z = DECAYF * ev.z + OMDF * sv.z;
    ne.w = DECAYF * ev.w + OMDF * sv.w;
    ((float4*)(out + offEma + (size_t)k * Dn))[t] = ne;
    float4 nc;
    nc.x = ne.x * inv; nc.y = ne.y * inv; nc.z = ne.z * inv; nc.w = ne.w * inv;
    ((float4*)(out + offCb + (size_t)k * Dn))[t] = nc;
}

// ---------------------------------------------------------------------------
extern "C" void kernel_launch(void* const* d_in, const int* in_sizes, int n_in,
                              void* d_out, int out_size) {
    const float* z_e    = (const float*)d_in[0];
    const float* cb     = (const float*)d_in[1];
    const float* ema_cs = (const float*)d_in[2];
    const float* ema_cb = (const float*)d_in[3];
    float* out = (float*)d_out;

    cudaFuncSetAttribute(gemm_kernel,
                         cudaFuncAttributeMaxDynamicSharedMemorySize, SMEM_BYTES);

    zero_kernel<<<4096, 256>>>();
    split_kernel<<<8192, 256>>>(z_e, 1, Bn * Dn);
    split_kernel<<<2048, 256>>>(cb,  0, Kn * Dn);
    csq_kernel<<<Kn / 8, 256>>>(cb);
    gemm_kernel<<<(Bn / 128) * (Kn / 128), 256, SMEM_BYTES>>>();
    select_kernel<<<Bn, 256>>>(z_e, cb);
    scatter_kernel<<<Bn, 128>>>(z_e, cb, out);
    ema_kernel<<<Kn, 128>>>(ema_cs, ema_cb, out);
}

// round 8
// speedup vs baseline: 6.1510x; 1.1548x over previous
#include <cuda_runtime.h>
#include <cuda_fp16.h>
#include <cstdint>

#define Bn 32768
#define Kn 8192
#define Dn 512
#define DECAYF 0.99f
#define OMDF   0.01f
#define EPSF   1e-5f

#define NITER 8              // K=512, BLK_K=64
#define STB 18432            // bytes per stage: 128 rows * 144B (128B data + 16 pad)
#define SM_CSQ  110592       // after 3*STB*2
#define SMEM_BYTES 111104

// Device scratch (allocation-free). NEVER referenced from host code.
__device__ uint4  g_A4[(size_t)Bn * Dn * 2 / 16];     // fp16 of z_e
__device__ uint4  g_B4[(size_t)Kn * Dn * 2 / 16];     // fp16 of codebook
__device__ __half g_scores[(size_t)Bn * Kn];          // approx scores
__device__ float  g_embed[(size_t)Kn * Dn];
__device__ float  g_counts[Kn];
__device__ float  g_csq[Kn];
__device__ unsigned g_cmax_bits;                      // max csq (float bits)

__device__ __forceinline__ uint32_t smem_u32(const void* p) {
    uint32_t a;
    asm("{ .reg .u64 t; cvta.to.shared.u64 t, %1; cvt.u32.u64 %0, t; }"
        : "=r"(a) : "l"(p));
    return a;
}
__device__ __forceinline__ void cpa16(uint32_t s, const void* g) {
    asm volatile("cp.async.cg.shared.global [%0], [%1], 16;" :: "r"(s), "l"(g));
}
#define CP_COMMIT() asm volatile("cp.async.commit_group;" ::: "memory")
#define CP_WAIT1()  asm volatile("cp.async.wait_group 1;" ::: "memory")

__device__ __forceinline__ void ldsm4(uint32_t& r0, uint32_t& r1, uint32_t& r2,
                                      uint32_t& r3, uint32_t addr) {
    asm volatile("ldmatrix.sync.aligned.m8n8.x4.shared.b16 {%0,%1,%2,%3}, [%4];"
                 : "=r"(r0), "=r"(r1), "=r"(r2), "=r"(r3) : "r"(addr));
}
__device__ __forceinline__ void hmma(float* c, uint32_t a0, uint32_t a1,
                                     uint32_t a2, uint32_t a3,
                                     uint32_t b0, uint32_t b1) {
    asm volatile(
        "mma.sync.aligned.m16n8k16.row.col.f32.f16.f16.f32 "
        "{%0,%1,%2,%3}, {%4,%5,%6,%7}, {%8,%9}, {%0,%1,%2,%3};"
        : "+f"(c[0]), "+f"(c[1]), "+f"(c[2]), "+f"(c[3])
        : "r"(a0), "r"(a1), "r"(a2), "r"(a3), "r"(b0), "r"(b1));
}
__device__ __forceinline__ unsigned f2ord(float f) {
    unsigned u = __float_as_uint(f);
    return (u & 0x80000000u) ? ~u : (u | 0x80000000u);
}

// ---------------------------------------------------------------------------
__global__ void zero_kernel() {
    int stride = gridDim.x * blockDim.x;
    int t = blockIdx.x * blockDim.x + threadIdx.x;
    const int N = Kn * Dn;
    for (int i = t; i < N; i += stride) g_embed[i] = 0.0f;
    if (t < Kn) g_counts[t] = 0.0f;
    if (t == 0) g_cmax_bits = 0u;
}

// z_e fp32 -> fp16, vectorized 4-wide
__global__ void splitA_kernel(const float* __restrict__ src) {
    ushort4* dst = (ushort4*)(void*)g_A4;
    int stride = gridDim.x * blockDim.x;
    const int n4 = Bn * Dn / 4;
    for (int i = blockIdx.x * blockDim.x + threadIdx.x; i < n4; i += stride) {
        float4 v = ((const float4*)src)[i];
        __half2 lo = __floats2half2_rn(v.x, v.y);
        __half2 hi = __floats2half2_rn(v.z, v.w);
        ushort4 o;
        o.x = *(unsigned short*)&lo;  o.y = ((unsigned short*)&lo)[1];
        o.z = *(unsigned short*)&hi;  o.w = ((unsigned short*)&hi)[1];
        dst[i] = o;
    }
}

// codebook fp32 -> fp16 AND csq, one warp per row
__global__ void splitB_csq_kernel(const float* __restrict__ cb) {
    int warp = (blockIdx.x * blockDim.x + threadIdx.x) >> 5;
    int lane = threadIdx.x & 31;
    if (warp >= Kn) return;
    const float4* row = (const float4*)(cb + (size_t)warp * Dn);
    ushort4* drow = (ushort4*)((__half*)(void*)g_B4 + (size_t)warp * Dn);
    float s = 0.0f;
    #pragma unroll
    for (int i = lane; i < Dn / 4; i += 32) {
        float4 v = row[i];
        s += v.x * v.x + v.y * v.y + v.z * v.z + v.w * v.w;
        __half2 lo = __floats2half2_rn(v.x, v.y);
        __half2 hi = __floats2half2_rn(v.z, v.w);
        ushort4 o;
        o.x = *(unsigned short*)&lo;  o.y = ((unsigned short*)&lo)[1];
        o.z = *(unsigned short*)&hi;  o.w = ((unsigned short*)&hi)[1];
        drow[i] = o;
    }
    #pragma unroll
    for (int o = 16; o > 0; o >>= 1) s += __shfl_xor_sync(0xFFFFFFFFu, s, o);
    if (lane == 0) {
        g_csq[warp] = s;
        atomicMax(&g_cmax_bits, __float_as_uint(s));  // s>0: bit order = float order
    }
}

// ---------------------------------------------------------------------------
// Pass 1: fp16 GEMM, scores (csq - 2*dot) streamed to g_scores as fp16.
// Block 128x128, 8 warps (4x2), BLK_K=64, 3-slot cp.async pipeline.
// ---------------------------------------------------------------------------
__global__ void __launch_bounds__(256, 2)
gemm_kernel() {
    extern __shared__ char sm[];
    const uint32_t sA = smem_u32(sm);
    const uint32_t sB = sA + 3 * STB;
    float* csq_s = (float*)(sm + SM_CSQ);

    const int tid = threadIdx.x;
    const int lane = tid & 31;
    const int w = tid >> 5;
    const int warpM = w & 3;
    const int warpN = w >> 2;
    const int rowBase = (blockIdx.x >> 6) * 128;
    const int colBase = (blockIdx.x & 63) * 128;   // colTile-fastest: B L2-resident

    if (tid < 128) csq_s[tid] = g_csq[colBase + tid];

    const __half* A = (const __half*)(void*)g_A4;
    const __half* Bm = (const __half*)(void*)g_B4;

    // loader: 1024 16B-chunks per matrix per stage; thread covers 4 (A) + 4 (B)
    const int lr = tid >> 3, lc = tid & 7;           // row 0..31, chunk 0..7
    const uint32_t soBase = (uint32_t)(lr * 144 + lc * 16);
    const __half* gA = A + (size_t)(rowBase + lr) * Dn + lc * 8;
    const __half* gB = Bm + (size_t)(colBase + lr) * Dn + lc * 8;

    float acc[2][8][4];
    #pragma unroll
    for (int mt = 0; mt < 2; mt++)
        #pragma unroll
        for (int nt = 0; nt < 8; nt++)
            #pragma unroll
            for (int r = 0; r < 4; r++) acc[mt][nt][r] = 0.0f;

    const int lrow = lane & 15;
    const int khalf = lane >> 4;
    const uint32_t aRowOff = (uint32_t)((warpM * 32 + lrow) * 144 + khalf * 16);
    const uint32_t bRowOff = (uint32_t)((warpN * 64 + lrow) * 144 + khalf * 16);

    #define LOAD_STAGE(s, slot) do {                                           \
        int _off = (s) << 6;                                                   \
        uint32_t _da = sA + (slot) * STB;                                      \
        uint32_t _db = sB + (slot) * STB;                                      \
        _Pragma("unroll")                                                      \
        for (int it = 0; it < 4; it++) {                                       \
            uint32_t so = soBase + it * 32 * 144;                              \
            cpa16(_da + so, gA + (size_t)(it * 32) * Dn + _off);               \
            cpa16(_db + so, gB + (size_t)(it * 32) * Dn + _off);               \
        }                                                                      \
    } while (0)

    LOAD_STAGE(0, 0); CP_COMMIT();
    LOAD_STAGE(1, 1); CP_COMMIT();

    int slot = 0, nslot = 2;
    #pragma unroll 1
    for (int s = 0; s < NITER; s++) {
        CP_WAIT1();
        __syncthreads();
        if (s + 2 < NITER) LOAD_STAGE(s + 2, nslot);
        CP_COMMIT();

        const uint32_t da = sA + slot * STB;
        const uint32_t db = sB + slot * STB;
        #pragma unroll
        for (int k16 = 0; k16 < 4; k16++) {
            uint32_t a[2][4];
            #pragma unroll
            for (int mt = 0; mt < 2; mt++)
                ldsm4(a[mt][0], a[mt][1], a[mt][2], a[mt][3],
                      da + aRowOff + mt * 16 * 144 + k16 * 32);
            uint32_t b[4][4];
            #pragma unroll
            for (int np = 0; np < 4; np++)
                ldsm4(b[np][0], b[np][1], b[np][2], b[np][3],
                      db + bRowOff + np * 16 * 144 + k16 * 32);
            #pragma unroll
            for (int mt = 0; mt < 2; mt++)
                #pragma unroll
                for (int nt = 0; nt < 8; nt++)
                    hmma(acc[mt][nt],
                         a[mt][0], a[mt][1], a[mt][2], a[mt][3],
                         b[nt >> 1][(nt & 1) ? 1 : 0],
                         b[nt >> 1][(nt & 1) ? 3 : 2]);
        }
        slot = slot == 2 ? 0 : slot + 1;
        nslot = nslot == 2 ? 0 : nslot + 1;
    }
    #undef LOAD_STAGE

    // epilogue: score = csq - 2*dot, streamed fp16 writes (evict-first)
    const int g = lane >> 2, tg = lane & 3;
    #pragma unroll
    for (int mt = 0; mt < 2; mt++) {
        #pragma unroll
        for (int half = 0; half < 2; half++) {
            int grow = rowBase + warpM * 32 + mt * 16 + half * 8 + g;
            unsigned* dst = (unsigned*)(g_scores + (size_t)grow * Kn + colBase);
            #pragma unroll
            for (int nt = 0; nt < 8; nt++) {
                int cl = warpN * 64 + nt * 8 + tg * 2;
                float s0 = fmaf(-2.0f, acc[mt][nt][half * 2 + 0], csq_s[cl]);
                float s1 = fmaf(-2.0f, acc[mt][nt][half * 2 + 1], csq_s[cl + 1]);
                __half2 h = __floats2half2_rn(s0, s1);
                __stcs(dst + (cl >> 1), *(unsigned*)&h);
            }
        }
    }
}

// ---------------------------------------------------------------------------
// Pass 2 (fused with scatter): scan scores, candidate rescore (exact fp32),
// write z_q + indices, atomic scatter counts/embed. One 256-thread block/row.
// ---------------------------------------------------------------------------
#define MAXCAND 128
__global__ void __launch_bounds__(256)
select_kernel(const float* __restrict__ z_e, const float* __restrict__ cb,
              float* __restrict__ out) {
    __shared__ float zs[Dn];
    __shared__ float rz[8], rs[8];
    __shared__ int list[MAXCAND];
    __shared__ int cnt;
    __shared__ float thrS;
    __shared__ unsigned long long bestPk;

    const int row = blockIdx.x;
    const int t = threadIdx.x;
    const int lane = t & 31, wid = t >> 5;

    // load z row + zsq
    float2 zv = ((const float2*)(z_e + (size_t)row * Dn))[t];
    ((float2*)zs)[t] = zv;
    float zp = zv.x * zv.x + zv.y * zv.y;
    #pragma unroll
    for (int o = 16; o > 0; o >>= 1) zp += __shfl_xor_sync(0xFFFFFFFFu, zp, o);
    if (lane == 0) rz[wid] = zp;
    if (t == 0) { cnt = 0; bestPk = 0xFFFFFFFFFFFFFFFFull; }

    // load 32 scores via 4 uint4 (evict-first), track min
    const uint4* sr = (const uint4*)(g_scores + (size_t)row * Kn);
    uint4 sv[4];
    float mn = 3.4e38f;
    #pragma unroll
    for (int i = 0; i < 4; i++) {
        sv[i] = __ldcs(sr + t + (i << 8));
        const unsigned* u = (const unsigned*)&sv[i];
        #pragma unroll
        for (int j = 0; j < 4; j++) {
            float2 f = __half22float2(*(const __half2*)&u[j]);
            mn = fminf(mn, fminf(f.x, f.y));
        }
    }
    #pragma unroll
    for (int o = 16; o > 0; o >>= 1) mn = fminf(mn, __shfl_xor_sync(0xFFFFFFFFu, mn, o));
    if (lane == 0) rs[wid] = mn;
    __syncthreads();
    if (t == 0) {
        float zsq = 0.0f, m = 3.4e38f;
        #pragma unroll
        for (int i = 0; i < 8; i++) { zsq += rz[i]; m = fminf(m, rs[i]); }
        float cmax = __uint_as_float(g_cmax_bits);
        // sound margin: dropped-products bound + fp16 quantization + slack
        thrS = m + 0.001953125f * sqrtf(zsq * cmax) + 4.5f;
    }
    __syncthreads();

    const float thr = thrS;
    #pragma unroll
    for (int i = 0; i < 4; i++) {
        const unsigned* u = (const unsigned*)&sv[i];
        #pragma unroll
        for (int j = 0; j < 4; j++) {
            float2 f = __half22float2(*(const __half2*)&u[j]);
            if (f.x <= thr) {
                int p = atomicAdd(&cnt, 1);
                if (p < MAXCAND) list[p] = (t + (i << 8)) * 8 + j * 2;
            }
            if (f.y <= thr) {
                int p = atomicAdd(&cnt, 1);
                if (p < MAXCAND) list[p] = (t + (i << 8)) * 8 + j * 2 + 1;
            }
        }
    }
    __syncthreads();

    if (cnt <= MAXCAND) {
        const int n = cnt;
        for (int j = wid; j < n; j += 8) {
            const int k = list[j];
            const float4* crow = (const float4*)(cb + (size_t)k * Dn);
            const float4* zrow = (const float4*)zs;
            float d = 0.0f;
            #pragma unroll
            for (int c = lane; c < Dn / 4; c += 32) {
                float4 a = zrow[c], b = crow[c];
                d += a.x * b.x + a.y * b.y + a.z * b.z + a.w * b.w;
            }
            #pragma unroll
            for (int o = 16; o > 0; o >>= 1) d += __shfl_xor_sync(0xFFFFFFFFu, d, o);
            if (lane == 0) {
                float ex = fmaf(-2.0f, d, g_csq[k]);
                unsigned long long pk =
                    ((unsigned long long)f2ord(ex) << 32) | (unsigned)k;
                atomicMin(&bestPk, pk);
            }
        }
    } else {
        // pathological overflow: exact brute force (sound fallback)
        for (int k = t; k < Kn; k += 256) {
            const float* crow = cb + (size_t)k * Dn;
            float d = 0.0f;
            for (int c = 0; c < Dn; c++) d += zs[c] * crow[c];
            float ex = fmaf(-2.0f, d, g_csq[k]);
            unsigned long long pk =
                ((unsigned long long)f2ord(ex) << 32) | (unsigned)k;
            atomicMin(&bestPk, pk);
        }
    }
    __syncthreads();

    // fused scatter: z_q, indices, counts, embed_sum
    const int idx = (int)(unsigned)(bestPk & 0xFFFFFFFFull);
    float2 cq = ((const float2*)(cb + (size_t)idx * Dn))[t];
    ((float2*)(out + (size_t)row * Dn))[t] = cq;       // z_q
    float* es = g_embed + (size_t)idx * Dn + t * 2;
    atomicAdd(es + 0, zv.x);
    atomicAdd(es + 1, zv.y);
    if (t == 0) {
        atomicAdd(&g_counts[idx], 1.0f);
        out[(size_t)Bn * Dn + row] = (float)idx;       // indices
    }
}

// ---------------------------------------------------------------------------
__global__ void ema_kernel(const float* __restrict__ ema_cs,
                           const float* __restrict__ ema_cb,
                           float* __restrict__ out) {
    const int k = blockIdx.x;
    const int t = threadIdx.x;

    const size_t offCb  = (size_t)Bn * Dn + Bn;
    const size_t offCs  = offCb + (size_t)Kn * Dn;
    const size_t offEma = offCs + Kn;

    float ncs = DECAYF * ema_cs[k] + OMDF * g_counts[k];
    float inv = 1.0f / (ncs + EPSF);
    if (t == 0) out[offCs + k] = ncs;

    float4 ev = ((const float4*)(ema_cb + (size_t)k * Dn))[t];
    float4 sv = ((const float4*)(g_embed + (size_t)k * Dn))[t];
    float4 ne;
    ne.x = DECAYF * ev.x + OMDF * sv.x;
    ne.y = DECAYF * ev.y + OMDF * sv.y;
    ne.z = DECAYF * ev.z + OMDF * sv.z;
    ne.w = DECAYF * ev.w + OMDF * sv.w;
    ((float4*)(out + offEma + (size_t)k * Dn))[t] = ne;
    float4 nc;
    nc.x = ne.x * inv; nc.y = ne.y * inv; nc.z = ne.z * inv; nc.w = ne.w * inv;
    ((float4*)(out + offCb + (size_t)k * Dn))[t] = nc;
}

// ---------------------------------------------------------------------------
extern "C" void kernel_launch(void* const* d_in, const int* in_sizes, int n_in,
                              void* d_out, int out_size) {
    const float* z_e    = (const float*)d_in[0];
    const float* cb     = (const float*)d_in[1];
    const float* ema_cs = (const float*)d_in[2];
    const float* ema_cb = (const float*)d_in[3];
    float* out = (float*)d_out;

    cudaFuncSetAttribute(gemm_kernel,
                         cudaFuncAttributeMaxDynamicSharedMemorySize, SMEM_BYTES);

    zero_kernel<<<4096, 256>>>();
    splitA_kernel<<<4096, 256>>>(z_e);
    splitB_csq_kernel<<<Kn / 8, 256>>>(cb);
    gemm_kernel<<<(Bn / 128) * (Kn / 128), 256, SMEM_BYTES>>>();
    select_kernel<<<Bn, 256>>>(z_e, cb, out);
    ema_kernel<<<Kn, 128>>>(ema_cs, ema_cb, out);
}